// round 1
// baseline (speedup 1.0000x reference)
#include <cuda_runtime.h>

#define N_ROWS   262144
#define MAXIT    100
#define RTOL     1e-5f
#define NNZ_CAP  4262144
#define TPB_CG   1024

struct __align__(8) Entry { int c; float v; };

// -------- static device scratch (no allocations allowed) --------
__device__ Entry   g_entries[NNZ_CAP];
__device__ int     g_rowptr[N_ROWS + 1];
__device__ int     g_cursor[N_ROWS];
__device__ float4  g_r[N_ROWS];
__device__ float4  g_p[N_ROWS];
__device__ float4  g_q[N_ROWS];
__device__ float   g_pq[MAXIT + 2];
__device__ float   g_rho[MAXIT + 2];
__device__ unsigned g_bar_count;
__device__ unsigned g_bar_gen;

// ---------------- setup kernels: build CSR each launch ----------------
__global__ void k_zero() {
    int i = blockIdx.x * blockDim.x + threadIdx.x;
    if (i < N_ROWS) g_cursor[i] = 0;
    if (i < MAXIT + 2) { g_pq[i] = 0.f; g_rho[i] = 0.f; }
    if (i == 0) { g_bar_count = 0u; g_bar_gen = 0u; }
}

__global__ void k_hist(const int* __restrict__ row, int nnz) {
    int i = blockIdx.x * blockDim.x + threadIdx.x;
    if (i < nnz) atomicAdd(&g_cursor[row[i]], 1);
}

// single-block exclusive scan over N_ROWS counts -> row_ptr (+ cursor copy)
__global__ void k_scan() {
    __shared__ int ssum[1024];
    const int t = threadIdx.x;
    const int CH = N_ROWS / 1024;
    const int base = t * CH;
    int s = 0;
#pragma unroll 8
    for (int j = 0; j < CH; ++j) s += g_cursor[base + j];
    ssum[t] = s;
    __syncthreads();
    for (int off = 1; off < 1024; off <<= 1) {
        int v = (t >= off) ? ssum[t - off] : 0;
        __syncthreads();
        ssum[t] += v;
        __syncthreads();
    }
    int run = ssum[t] - s;   // exclusive prefix of this thread's chunk
    for (int j = 0; j < CH; ++j) {
        int c = g_cursor[base + j];
        g_rowptr[base + j] = run;
        g_cursor[base + j] = run;
        run += c;
    }
    if (t == 1023) g_rowptr[N_ROWS] = run;
}

__global__ void k_scatter(const int* __restrict__ row, const int* __restrict__ col,
                          const float* __restrict__ val, int nnz) {
    int i = blockIdx.x * blockDim.x + threadIdx.x;
    if (i < nnz) {
        int r = row[i];
        int pos = atomicAdd(&g_cursor[r], 1);
        Entry e; e.c = col[i]; e.v = val[i];
        g_entries[pos] = e;
    }
}

// ---------------- persistent CG kernel ----------------
// Manual grid barrier. Grid is sized with the occupancy API so every block is
// co-resident (single wave) -> spin-wait is safe. Monotonic count, no reset.
__device__ __forceinline__ void grid_bar() {
    __syncthreads();
    if (threadIdx.x == 0) {
        __threadfence();
        unsigned gen = *((volatile unsigned*)&g_bar_gen);
        unsigned t = atomicAdd(&g_bar_count, 1u);
        if (t == (gen + 1u) * gridDim.x - 1u) {
            atomicAdd(&g_bar_gen, 1u);     // release
        } else {
            while (*((volatile unsigned*)&g_bar_gen) == gen) { }
        }
        __threadfence();
    }
    __syncthreads();
}

__device__ __forceinline__ void block_reduce_add(float v, float* target, float* sred) {
#pragma unroll
    for (int o = 16; o; o >>= 1) v += __shfl_down_sync(0xffffffffu, v, o);
    int wid = threadIdx.x >> 5;
    if ((threadIdx.x & 31) == 0) sred[wid] = v;
    __syncthreads();
    if (threadIdx.x < 32) {
        float x = (threadIdx.x < (blockDim.x >> 5)) ? sred[threadIdx.x] : 0.f;
#pragma unroll
        for (int o = 16; o; o >>= 1) x += __shfl_down_sync(0xffffffffu, x, o);
        if (threadIdx.x == 0) atomicAdd(target, x);
    }
    __syncthreads();
}

__global__ void __launch_bounds__(TPB_CG)
k_cg(const float4* __restrict__ b, float4* __restrict__ x) {
    __shared__ float sred[32];
    const int tid      = threadIdx.x;
    const int gtid     = blockIdx.x * TPB_CG + tid;
    const int nthreads = gridDim.x * TPB_CG;
    const int lane     = tid & 31;
    const int gwarp    = gtid >> 5;
    const int nwarps   = nthreads >> 5;

    // ---- phase 0: x=0, r=b, p=b, rho0 = b.b ----
    float acc = 0.f;
    for (int i = gtid; i < N_ROWS; i += nthreads) {
        float4 bv = b[i];
        x[i] = make_float4(0.f, 0.f, 0.f, 0.f);
        g_r[i] = bv;
        g_p[i] = bv;
        acc += bv.x * bv.x + bv.y * bv.y + bv.z * bv.z + bv.w * bv.w;
    }
    block_reduce_add(acc, &g_rho[0], sred);
    grid_bar();

    float rho_prev = *((volatile float*)&g_rho[0]);
    // tighter than reference (0.25x) for output-match margin; reference's own
    // truncation error dominates the comparison.
    const float tol2 = 0.25f * (RTOL * RTOL) * rho_prev;

    for (int k = 1; k <= MAXIT; ++k) {
        // ---- SpMV: q = A p, fused pq = p.q (warp per row) ----
        float pq = 0.f;
        for (int r = gwarp; r < N_ROWS; r += nwarps) {
            int s = g_rowptr[r];
            int e = g_rowptr[r + 1];
            float ax = 0.f, ay = 0.f, az = 0.f, aw = 0.f;
            for (int j = s + lane; j < e; j += 32) {
                Entry en = g_entries[j];                 // LDG.64, coalesced
                float4 pv = __ldcg(&g_p[en.c]);          // L2 (avoid stale L1)
                ax = fmaf(en.v, pv.x, ax);
                ay = fmaf(en.v, pv.y, ay);
                az = fmaf(en.v, pv.z, az);
                aw = fmaf(en.v, pv.w, aw);
            }
#pragma unroll
            for (int o = 16; o; o >>= 1) {
                ax += __shfl_down_sync(0xffffffffu, ax, o);
                ay += __shfl_down_sync(0xffffffffu, ay, o);
                az += __shfl_down_sync(0xffffffffu, az, o);
                aw += __shfl_down_sync(0xffffffffu, aw, o);
            }
            if (lane == 0) {
                g_q[r] = make_float4(ax, ay, az, aw);
                float4 pr = __ldcg(&g_p[r]);
                pq += ax * pr.x + ay * pr.y + az * pr.z + aw * pr.w;
            }
        }
        block_reduce_add(pq, &g_pq[k], sred);
        grid_bar();

        // ---- update x, r; rho_new = r.r ----
        float alpha = rho_prev / (*((volatile float*)&g_pq[k]));
        float rr = 0.f;
        for (int i = gtid; i < N_ROWS; i += nthreads) {
            float4 pv = g_p[i];                          // same-thread owner
            float4 qv = __ldcg(&g_q[i]);                 // cross-thread -> L2
            float4 xv = x[i];
            xv.x = fmaf(alpha, pv.x, xv.x); xv.y = fmaf(alpha, pv.y, xv.y);
            xv.z = fmaf(alpha, pv.z, xv.z); xv.w = fmaf(alpha, pv.w, xv.w);
            x[i] = xv;
            float4 rv = g_r[i];
            rv.x = fmaf(-alpha, qv.x, rv.x); rv.y = fmaf(-alpha, qv.y, rv.y);
            rv.z = fmaf(-alpha, qv.z, rv.z); rv.w = fmaf(-alpha, qv.w, rv.w);
            g_r[i] = rv;
            rr += rv.x * rv.x + rv.y * rv.y + rv.z * rv.z + rv.w * rv.w;
        }
        block_reduce_add(rr, &g_rho[k], sred);
        grid_bar();

        float rho_new = *((volatile float*)&g_rho[k]);
        float beta = rho_new / rho_prev;
        rho_prev = rho_new;
        if (rho_new <= tol2 || k == MAXIT) break;        // uniform decision

        // ---- p = r + beta * p ----
        for (int i = gtid; i < N_ROWS; i += nthreads) {
            float4 rv = g_r[i];
            float4 pv = g_p[i];
            pv.x = fmaf(beta, pv.x, rv.x); pv.y = fmaf(beta, pv.y, rv.y);
            pv.z = fmaf(beta, pv.z, rv.z); pv.w = fmaf(beta, pv.w, rv.w);
            g_p[i] = pv;
        }
        grid_bar();
    }
}

// ---------------- launch ----------------
extern "C" void kernel_launch(void* const* d_in, const int* in_sizes, int n_in,
                              void* d_out, int out_size) {
    const float* values = (const float*)d_in[0];
    const float4* b     = (const float4*)d_in[1];
    const int*   row    = (const int*)d_in[2];
    const int*   col    = (const int*)d_in[3];
    float4* x           = (float4*)d_out;
    const int nnz       = in_sizes[0];

    k_zero<<<(N_ROWS + 255) / 256, 256>>>();
    k_hist<<<(nnz + 255) / 256, 256>>>(row, nnz);
    k_scan<<<1, 1024>>>();
    k_scatter<<<(nnz + 255) / 256, 256>>>(row, col, values, nnz);

    int sm = 148, occ = 1;
    cudaDeviceGetAttribute(&sm, cudaDevAttrMultiProcessorCount, 0);
    cudaOccupancyMaxActiveBlocksPerMultiprocessor(&occ, k_cg, TPB_CG, 0);
    if (occ < 1) occ = 1;
    int grid = sm * occ;                 // exactly one co-resident wave
    k_cg<<<grid, TPB_CG>>>(b, x);
}

// round 3
// speedup vs baseline: 1.3876x; 1.3876x over previous
#include <cuda_runtime.h>

#define N_ROWS   262144
#define MAXIT    100
#define RTOL     1e-5f
#define NNZ_CAP  4262144
#define TPB_CG   1024
#define SUB_LG   4                 // 16-lane subwarp per row
#define SUB_SZ   (1 << SUB_LG)

struct __align__(8) Entry { int c; float v; };

// -------- static device scratch (no allocations allowed) --------
__device__ Entry   g_entries[NNZ_CAP];
__device__ int     g_rowptr[N_ROWS + 1];
__device__ int     g_cursor[N_ROWS];
__device__ float   g_diag[N_ROWS];
__device__ float   g_invd[N_ROWS];
__device__ float4  g_r[N_ROWS];
__device__ float4  g_p[N_ROWS];
__device__ float4  g_q[N_ROWS];
__device__ float   g_pq[MAXIT + 2];
__device__ float   g_rr[MAXIT + 2];
__device__ float   g_rz[MAXIT + 2];
__device__ unsigned g_bar_count;
__device__ unsigned g_bar_gen;

// ---------------- setup kernels: build CSR + diag each launch ----------------
__global__ void k_zero() {
    int i = blockIdx.x * blockDim.x + threadIdx.x;
    if (i < N_ROWS) { g_cursor[i] = 0; g_diag[i] = 0.f; }
    if (i < MAXIT + 2) { g_pq[i] = 0.f; g_rr[i] = 0.f; g_rz[i] = 0.f; }
    if (i == 0) { g_bar_count = 0u; g_bar_gen = 0u; }
}

__global__ void k_hist(const int* __restrict__ row, const int* __restrict__ col,
                       const float* __restrict__ val, int nnz) {
    int i = blockIdx.x * blockDim.x + threadIdx.x;
    if (i < nnz) {
        int r = row[i];
        atomicAdd(&g_cursor[r], 1);
        if (col[i] == r) atomicAdd(&g_diag[r], val[i]);   // true matrix diagonal
    }
}

// single-block exclusive scan over N_ROWS counts -> row_ptr (+ cursor copy)
__global__ void k_scan() {
    __shared__ int ssum[1024];
    const int t = threadIdx.x;
    const int CH = N_ROWS / 1024;
    const int base = t * CH;
    int s = 0;
#pragma unroll 8
    for (int j = 0; j < CH; ++j) s += g_cursor[base + j];
    ssum[t] = s;
    __syncthreads();
    for (int off = 1; off < 1024; off <<= 1) {
        int v = (t >= off) ? ssum[t - off] : 0;
        __syncthreads();
        ssum[t] += v;
        __syncthreads();
    }
    int run = ssum[t] - s;
    for (int j = 0; j < CH; ++j) {
        int c = g_cursor[base + j];
        g_rowptr[base + j] = run;
        g_cursor[base + j] = run;
        run += c;
        g_invd[base + j] = 1.0f / g_diag[base + j];       // Jacobi inverse diag
    }
    if (t == 1023) g_rowptr[N_ROWS] = run;
}

__global__ void k_scatter(const int* __restrict__ row, const int* __restrict__ col,
                          const float* __restrict__ val, int nnz) {
    int i = blockIdx.x * blockDim.x + threadIdx.x;
    if (i < nnz) {
        int r = row[i];
        int pos = atomicAdd(&g_cursor[r], 1);
        Entry e; e.c = col[i]; e.v = val[i];
        g_entries[pos] = e;
    }
}

// ---------------- persistent PCG kernel ----------------
__device__ __forceinline__ void grid_bar() {
    __syncthreads();
    if (threadIdx.x == 0) {
        __threadfence();
        unsigned gen = *((volatile unsigned*)&g_bar_gen);
        unsigned t = atomicAdd(&g_bar_count, 1u);
        if (t == (gen + 1u) * gridDim.x - 1u) {
            atomicAdd(&g_bar_gen, 1u);
        } else {
            while (*((volatile unsigned*)&g_bar_gen) == gen) { }
        }
        __threadfence();
    }
    __syncthreads();
}

__device__ __forceinline__ void block_reduce_add(float v, float* target, float* sred) {
#pragma unroll
    for (int o = 16; o; o >>= 1) v += __shfl_down_sync(0xffffffffu, v, o);
    int wid = threadIdx.x >> 5;
    if ((threadIdx.x & 31) == 0) sred[wid] = v;
    __syncthreads();
    if (threadIdx.x < 32) {
        float x = (threadIdx.x < (blockDim.x >> 5)) ? sred[threadIdx.x] : 0.f;
#pragma unroll
        for (int o = 16; o; o >>= 1) x += __shfl_down_sync(0xffffffffu, x, o);
        if (threadIdx.x == 0) atomicAdd(target, x);
    }
    __syncthreads();
}

__global__ void __launch_bounds__(TPB_CG)
k_cg(const float4* __restrict__ b, float4* __restrict__ x) {
    __shared__ float sred[32];
    const int tid      = threadIdx.x;
    const int gtid     = blockIdx.x * TPB_CG + tid;
    const int nthreads = gridDim.x * TPB_CG;
    const int sl       = tid & (SUB_SZ - 1);
    const int gsub     = (blockIdx.x * TPB_CG + tid) >> SUB_LG;
    const int nsub     = nthreads >> SUB_LG;

    // ---- phase 0: x=0, r=b, p=invd*b, rz0 = b.(invd*b), bb = b.b ----
    float rz = 0.f, bb = 0.f;
    for (int i = gtid; i < N_ROWS; i += nthreads) {
        float4 bv = b[i];
        float id = g_invd[i];
        x[i] = make_float4(0.f, 0.f, 0.f, 0.f);
        g_r[i] = bv;
        g_p[i] = make_float4(id * bv.x, id * bv.y, id * bv.z, id * bv.w);
        bb += bv.x * bv.x + bv.y * bv.y + bv.z * bv.z + bv.w * bv.w;
        rz += id * (bv.x * bv.x + bv.y * bv.y + bv.z * bv.z + bv.w * bv.w);
    }
    block_reduce_add(rz, &g_rz[0], sred);
    block_reduce_add(bb, &g_rr[0], sred);
    grid_bar();

    float rho   = *((volatile float*)&g_rz[0]);
    const float tol2 = 0.25f * (RTOL * RTOL) * (*((volatile float*)&g_rr[0]));

    for (int k = 1; k <= MAXIT; ++k) {
        // ---- phase A: q = A p (16-lane subwarp per row), pq = p.q ----
        float pq = 0.f;
        for (int r = gsub; r < N_ROWS; r += nsub) {
            int s = __ldg(&g_rowptr[r]);
            int e = __ldg(&g_rowptr[r + 1]);
            float ax = 0.f, ay = 0.f, az = 0.f, aw = 0.f;
            for (int j = s + sl; j < e; j += SUB_SZ) {
                int2 raw = __ldg((const int2*)&g_entries[j]);   // LDG.64 read-only
                int   ec = raw.x;
                float ev = __int_as_float(raw.y);
                float4 pv = __ldcg(&g_p[ec]);            // L2 (cross-SM data)
                ax = fmaf(ev, pv.x, ax);
                ay = fmaf(ev, pv.y, ay);
                az = fmaf(ev, pv.z, az);
                aw = fmaf(ev, pv.w, aw);
            }
#pragma unroll
            for (int o = SUB_SZ / 2; o; o >>= 1) {
                ax += __shfl_down_sync(0xffffffffu, ax, o, SUB_SZ);
                ay += __shfl_down_sync(0xffffffffu, ay, o, SUB_SZ);
                az += __shfl_down_sync(0xffffffffu, az, o, SUB_SZ);
                aw += __shfl_down_sync(0xffffffffu, aw, o, SUB_SZ);
            }
            if (sl == 0) {
                g_q[r] = make_float4(ax, ay, az, aw);
                float4 pr = __ldcg(&g_p[r]);
                pq += ax * pr.x + ay * pr.y + az * pr.z + aw * pr.w;
            }
        }
        block_reduce_add(pq, &g_pq[k], sred);
        grid_bar();

        // ---- phase B: x += a p, r -= a q;  rr = r.r, rz = r.(invd r) ----
        float alpha = rho / (*((volatile float*)&g_pq[k]));
        float rr = 0.f;
        float rzn = 0.f;
        for (int i = gtid; i < N_ROWS; i += nthreads) {
            float4 pv = g_p[i];
            float4 qv = __ldcg(&g_q[i]);
            float4 xv = x[i];
            xv.x = fmaf(alpha, pv.x, xv.x); xv.y = fmaf(alpha, pv.y, xv.y);
            xv.z = fmaf(alpha, pv.z, xv.z); xv.w = fmaf(alpha, pv.w, xv.w);
            x[i] = xv;
            float4 rv = g_r[i];
            rv.x = fmaf(-alpha, qv.x, rv.x); rv.y = fmaf(-alpha, qv.y, rv.y);
            rv.z = fmaf(-alpha, qv.z, rv.z); rv.w = fmaf(-alpha, qv.w, rv.w);
            g_r[i] = rv;
            float s2 = rv.x * rv.x + rv.y * rv.y + rv.z * rv.z + rv.w * rv.w;
            rr  += s2;
            rzn += g_invd[i] * s2;
        }
        block_reduce_add(rr,  &g_rr[k], sred);
        block_reduce_add(rzn, &g_rz[k], sred);
        grid_bar();

        float rr_g = *((volatile float*)&g_rr[k]);
        float rz_g = *((volatile float*)&g_rz[k]);
        float beta = rz_g / rho;
        rho = rz_g;
        if (rr_g <= tol2 || k == MAXIT) break;           // uniform decision

        // ---- phase C: p = invd*r + beta*p ----
        for (int i = gtid; i < N_ROWS; i += nthreads) {
            float4 rv = g_r[i];
            float4 pv = g_p[i];
            float id = g_invd[i];
            pv.x = fmaf(beta, pv.x, id * rv.x); pv.y = fmaf(beta, pv.y, id * rv.y);
            pv.z = fmaf(beta, pv.z, id * rv.z); pv.w = fmaf(beta, pv.w, id * rv.w);
            g_p[i] = pv;
        }
        grid_bar();
    }
}

// ---------------- launch ----------------
extern "C" void kernel_launch(void* const* d_in, const int* in_sizes, int n_in,
                              void* d_out, int out_size) {
    const float* values = (const float*)d_in[0];
    const float4* b     = (const float4*)d_in[1];
    const int*   row    = (const int*)d_in[2];
    const int*   col    = (const int*)d_in[3];
    float4* x           = (float4*)d_out;
    const int nnz       = in_sizes[0];

    k_zero<<<(N_ROWS + 255) / 256, 256>>>();
    k_hist<<<(nnz + 255) / 256, 256>>>(row, col, values, nnz);
    k_scan<<<1, 1024>>>();
    k_scatter<<<(nnz + 255) / 256, 256>>>(row, col, values, nnz);

    int sm = 148, occ = 1;
    cudaDeviceGetAttribute(&sm, cudaDevAttrMultiProcessorCount, 0);
    cudaOccupancyMaxActiveBlocksPerMultiprocessor(&occ, k_cg, TPB_CG, 0);
    if (occ < 1) occ = 1;
    int grid = sm * occ;                 // one co-resident wave
    k_cg<<<grid, TPB_CG>>>(b, x);
}

// round 4
// speedup vs baseline: 1.4679x; 1.0579x over previous
#include <cuda_runtime.h>

#define N_ROWS   262144
#define MAXIT    100
#define RTOL     1e-5f
#define NNZ_CAP  4262144
#define TPB_CG   1024
#define SUB_LG   3                 // 8-lane subwarp, 2 entries per lane
#define SUB_SZ   (1 << SUB_LG)

struct __align__(8) Entry { int c; float v; };

// -------- static device scratch (no allocations allowed) --------
__device__ Entry   g_entries[NNZ_CAP];     // off-diagonal only, rows padded to even
__device__ int     g_rowptr[N_ROWS + 1];
__device__ int     g_cursor[N_ROWS];
__device__ float   g_diag[N_ROWS];
__device__ float   g_invd[N_ROWS];
__device__ float4  g_r[N_ROWS];
__device__ float4  g_z[N_ROWS];
__device__ float4  g_p[N_ROWS];
__device__ float4  g_q[N_ROWS];
__device__ float4  g_w[N_ROWS];
__device__ float   g_rz[MAXIT + 2];
__device__ float   g_wz[MAXIT + 2];
__device__ float   g_rr[MAXIT + 2];
__device__ unsigned g_bar_count;
__device__ unsigned g_bar_gen;

// ---------------- setup: build padded off-diag CSR + diag ----------------
__global__ void k_zero() {
    int i = blockIdx.x * blockDim.x + threadIdx.x;
    if (i < N_ROWS) { g_cursor[i] = 0; g_diag[i] = 0.f; }
    if (i < MAXIT + 2) { g_rz[i] = 0.f; g_wz[i] = 0.f; g_rr[i] = 0.f; }
    if (i == 0) { g_bar_count = 0u; g_bar_gen = 0u; }
}

__global__ void k_hist(const int* __restrict__ row, const int* __restrict__ col,
                       const float* __restrict__ val, int nnz) {
    int i = blockIdx.x * blockDim.x + threadIdx.x;
    if (i < nnz) {
        int r = row[i];
        if (col[i] == r) atomicAdd(&g_diag[r], val[i]);   // all diagonal mass
        else             atomicAdd(&g_cursor[r], 1);
    }
}

// single-block scan: padded (even) row starts; cursor=start; invd=1/diag
__global__ void k_scan() {
    __shared__ int ssum[1024];
    const int t = threadIdx.x;
    const int CH = N_ROWS / 1024;
    const int base = t * CH;
    int s = 0;
#pragma unroll 8
    for (int j = 0; j < CH; ++j) s += (g_cursor[base + j] + 1) & ~1;
    ssum[t] = s;
    __syncthreads();
    for (int off = 1; off < 1024; off <<= 1) {
        int v = (t >= off) ? ssum[t - off] : 0;
        __syncthreads();
        ssum[t] += v;
        __syncthreads();
    }
    int run = ssum[t] - s;
    for (int j = 0; j < CH; ++j) {
        int c = (g_cursor[base + j] + 1) & ~1;
        g_rowptr[base + j] = run;
        g_cursor[base + j] = run;
        run += c;
        g_invd[base + j] = 1.0f / g_diag[base + j];
    }
    if (t == 1023) g_rowptr[N_ROWS] = run;
}

__global__ void k_scatter(const int* __restrict__ row, const int* __restrict__ col,
                          const float* __restrict__ val, int nnz) {
    int i = blockIdx.x * blockDim.x + threadIdx.x;
    if (i < nnz) {
        int r = row[i];
        int c = col[i];
        if (c != r) {
            int pos = atomicAdd(&g_cursor[r], 1);
            Entry e; e.c = c; e.v = val[i];
            g_entries[pos] = e;
        }
    }
}

// zero the single padding slot of odd-length rows
__global__ void k_pad() {
    int r = blockIdx.x * blockDim.x + threadIdx.x;
    if (r < N_ROWS) {
        int cur = g_cursor[r];
        if (cur < g_rowptr[r + 1]) {       // odd count -> one hole
            Entry e; e.c = 0; e.v = 0.f;
            g_entries[cur] = e;
        }
    }
}

// ---------------- persistent Chronopoulos-Gear PCG ----------------
__device__ __forceinline__ void grid_bar() {
    __syncthreads();
    if (threadIdx.x == 0) {
        __threadfence();
        unsigned gen = *((volatile unsigned*)&g_bar_gen);
        unsigned t = atomicAdd(&g_bar_count, 1u);
        if (t == (gen + 1u) * gridDim.x - 1u) {
            atomicAdd(&g_bar_gen, 1u);
        } else {
            while (*((volatile unsigned*)&g_bar_gen) == gen) { }
        }
        __threadfence();
    }
    __syncthreads();
}

__device__ __forceinline__ void block_reduce_add(float v, float* target, float* sred) {
#pragma unroll
    for (int o = 16; o; o >>= 1) v += __shfl_down_sync(0xffffffffu, v, o);
    int wid = threadIdx.x >> 5;
    if ((threadIdx.x & 31) == 0) sred[wid] = v;
    __syncthreads();
    if (threadIdx.x < 32) {
        float x = (threadIdx.x < (blockDim.x >> 5)) ? sred[threadIdx.x] : 0.f;
#pragma unroll
        for (int o = 16; o; o >>= 1) x += __shfl_down_sync(0xffffffffu, x, o);
        if (threadIdx.x == 0) atomicAdd(target, x);
    }
    __syncthreads();
}

__global__ void __launch_bounds__(TPB_CG)
k_cg(const float4* __restrict__ b, float4* __restrict__ x) {
    __shared__ float sred[32];
    const int tid      = threadIdx.x;
    const int gtid     = blockIdx.x * TPB_CG + tid;
    const int nthreads = gridDim.x * TPB_CG;
    const int sl       = tid & (SUB_SZ - 1);
    const int gsub     = gtid >> SUB_LG;
    const int nsub     = nthreads >> SUB_LG;

    // ---- init: x=0, r=b, z=invd*b; bb for tolerance ----
    float bb = 0.f;
    for (int i = gtid; i < N_ROWS; i += nthreads) {
        float4 bv = b[i];
        float id = g_invd[i];
        x[i]   = make_float4(0.f, 0.f, 0.f, 0.f);
        g_r[i] = bv;
        g_z[i] = make_float4(id * bv.x, id * bv.y, id * bv.z, id * bv.w);
        bb += bv.x * bv.x + bv.y * bv.y + bv.z * bv.z + bv.w * bv.w;
    }
    block_reduce_add(bb, &g_rr[0], sred);
    grid_bar();

    const float tol2 = (RTOL * RTOL) * (*((volatile float*)&g_rr[0]));
    float rz_prev = 1.f, alpha_prev = 1.f;

    for (int k = 1; k <= MAXIT; ++k) {
        // ---- phase A: w = A z ; fused rz=(r,z), wz=(w,z) ----
        float rz = 0.f, wz = 0.f;
        for (int r = gsub; r < N_ROWS; r += nsub) {
            int s = __ldg(&g_rowptr[r]);
            int e = __ldg(&g_rowptr[r + 1]);
            float ax = 0.f, ay = 0.f, az = 0.f, aw = 0.f;
            for (int j = s + 2 * sl; j < e; j += 2 * SUB_SZ) {
                int4 raw = __ldg((const int4*)&g_entries[j]);   // 2 entries, LDG.128
                float ev0 = __int_as_float(raw.y);
                float ev1 = __int_as_float(raw.w);
                float4 z0 = __ldcg(&g_z[raw.x]);                // 2 independent gathers
                float4 z1 = __ldcg(&g_z[raw.z]);
                ax = fmaf(ev0, z0.x, ax); ay = fmaf(ev0, z0.y, ay);
                az = fmaf(ev0, z0.z, az); aw = fmaf(ev0, z0.w, aw);
                ax = fmaf(ev1, z1.x, ax); ay = fmaf(ev1, z1.y, ay);
                az = fmaf(ev1, z1.z, az); aw = fmaf(ev1, z1.w, aw);
            }
#pragma unroll
            for (int o = SUB_SZ / 2; o; o >>= 1) {
                ax += __shfl_down_sync(0xffffffffu, ax, o, SUB_SZ);
                ay += __shfl_down_sync(0xffffffffu, ay, o, SUB_SZ);
                az += __shfl_down_sync(0xffffffffu, az, o, SUB_SZ);
                aw += __shfl_down_sync(0xffffffffu, aw, o, SUB_SZ);
            }
            if (sl == 0) {
                float4 zr = __ldcg(&g_z[r]);
                float  d  = __ldg(&g_diag[r]);
                ax = fmaf(d, zr.x, ax); ay = fmaf(d, zr.y, ay);
                az = fmaf(d, zr.z, az); aw = fmaf(d, zr.w, aw);
                g_w[r] = make_float4(ax, ay, az, aw);
                float4 rv = __ldcg(&g_r[r]);
                rz += rv.x * zr.x + rv.y * zr.y + rv.z * zr.z + rv.w * zr.w;
                wz += ax * zr.x + ay * zr.y + az * zr.z + aw * zr.w;
            }
        }
        block_reduce_add(rz, &g_rz[k], sred);
        block_reduce_add(wz, &g_wz[k], sred);
        grid_bar();

        // ---- scalars (uniform across all threads) ----
        float rzv = *((volatile float*)&g_rz[k]);
        float wzv = *((volatile float*)&g_wz[k]);
        float beta, alpha;
        if (k == 1) { beta = 0.f; alpha = rzv / wzv; }
        else {
            beta  = rzv / rz_prev;
            alpha = rzv / (wzv - beta * rzv / alpha_prev);
        }
        rz_prev = rzv; alpha_prev = alpha;

        // ---- phase B: p=z+beta p; q=w+beta q; x+=a p; r-=a q; z=invd r; rr ----
        float rr = 0.f;
        for (int i = gtid; i < N_ROWS; i += nthreads) {
            float4 zv = g_z[i];                      // self-owned
            float4 wv = __ldcg(&g_w[i]);             // cross-thread writer
            float4 pv, qv;
            if (k == 1) { pv = zv; qv = wv; }
            else {
                pv = g_p[i]; qv = g_q[i];            // self-owned
                pv.x = fmaf(beta, pv.x, zv.x); pv.y = fmaf(beta, pv.y, zv.y);
                pv.z = fmaf(beta, pv.z, zv.z); pv.w = fmaf(beta, pv.w, zv.w);
                qv.x = fmaf(beta, qv.x, wv.x); qv.y = fmaf(beta, qv.y, wv.y);
                qv.z = fmaf(beta, qv.z, wv.z); qv.w = fmaf(beta, qv.w, wv.w);
            }
            g_p[i] = pv; g_q[i] = qv;
            float4 xv = x[i];
            xv.x = fmaf(alpha, pv.x, xv.x); xv.y = fmaf(alpha, pv.y, xv.y);
            xv.z = fmaf(alpha, pv.z, xv.z); xv.w = fmaf(alpha, pv.w, xv.w);
            x[i] = xv;
            float4 rv = g_r[i];
            rv.x = fmaf(-alpha, qv.x, rv.x); rv.y = fmaf(-alpha, qv.y, rv.y);
            rv.z = fmaf(-alpha, qv.z, rv.z); rv.w = fmaf(-alpha, qv.w, rv.w);
            g_r[i] = rv;
            rr += rv.x * rv.x + rv.y * rv.y + rv.z * rv.z + rv.w * rv.w;
            float id = g_invd[i];
            g_z[i] = make_float4(id * rv.x, id * rv.y, id * rv.z, id * rv.w);
        }
        block_reduce_add(rr, &g_rr[k], sred);
        grid_bar();

        float rr_g = *((volatile float*)&g_rr[k]);
        if (rr_g <= tol2 || k == MAXIT) break;       // uniform decision
    }
}

// ---------------- launch ----------------
extern "C" void kernel_launch(void* const* d_in, const int* in_sizes, int n_in,
                              void* d_out, int out_size) {
    const float* values = (const float*)d_in[0];
    const float4* b     = (const float4*)d_in[1];
    const int*   row    = (const int*)d_in[2];
    const int*   col    = (const int*)d_in[3];
    float4* x           = (float4*)d_out;
    const int nnz       = in_sizes[0];

    k_zero<<<(N_ROWS + 255) / 256, 256>>>();
    k_hist<<<(nnz + 255) / 256, 256>>>(row, col, values, nnz);
    k_scan<<<1, 1024>>>();
    k_scatter<<<(nnz + 255) / 256, 256>>>(row, col, values, nnz);
    k_pad<<<(N_ROWS + 255) / 256, 256>>>();

    int sm = 148, occ = 1;
    cudaDeviceGetAttribute(&sm, cudaDevAttrMultiProcessorCount, 0);
    cudaOccupancyMaxActiveBlocksPerMultiprocessor(&occ, k_cg, TPB_CG, 0);
    if (occ < 1) occ = 1;
    int grid = sm * occ;                 // one co-resident wave
    k_cg<<<grid, TPB_CG>>>(b, x);
}